// round 5
// baseline (speedup 1.0000x reference)
#include <cuda_runtime.h>
#include <cuda_fp16.h>
#include <cstdint>

#define BATCH 8
#define NPTS 200000
#define CH 32
#define RES 128
#define NBINS (RES * RES)
#define NSEG (BATCH * 3)
#define CAP 16
#define EPSF 1e-5f

// Per-BATCH bucketed feature slabs (reused across the 8 batches):
// slot = 64B = 16 half2 = 32 channels (f16). 3*16384*16 slots = 50.3 MB -> L2-resident.
__device__ uint4 g_slab[(size_t)3 * NBINS * CAP * 4];
// Per-batch bin counters (reset by mean_kernel after use).
__device__ unsigned g_cnt[3 * NBINS];
// fp32 overflow accumulator for the rare cnt>CAP points; sparse, self-cleaning.
__device__ float g_ovf[(size_t)NSEG * NBINS * CH];

__device__ __forceinline__ void red_add_v4(float* addr, float a, float b, float c, float d) {
    asm volatile("red.global.add.v4.f32 [%0], {%1, %2, %3, %4};"
                 :: "l"(addr), "f"(a), "f"(b), "f"(c), "f"(d)
                 : "memory");
}

__device__ __forceinline__ int to_bin(float v) {
    // Byte-identical to the validated Round-1 formula (matches JAX exactly).
    float t = (v + 1.0f) / 2.0f - 0.5f;
    t = t / (1.0f + EPSF) + 0.5f;
    t = fminf(fmaxf(t, 0.0f), 1.0f - EPSF);
    return (int)(t * 128.0f);
}

// Fused transpose + bin + bucketed payload scatter for ONE batch.
// grid ceil(NPTS/256), block 256. Thread = one point.
__global__ void scatter_kernel(const float* __restrict__ xyz,
                               const float* __restrict__ feat, int b) {
    __shared__ float s[CH][257];
    int n0 = blockIdx.x * 256;
    int t = threadIdx.x;
    int n = n0 + t;
    bool valid = n < NPTS;

    const float* fb = feat + (size_t)b * CH * NPTS;
#pragma unroll
    for (int c = 0; c < CH; c++)
        s[c][t] = valid ? fb[(size_t)c * NPTS + n] : 0.f;
    __syncthreads();
    if (!valid) return;

    // Pack this point's 32 channels into 16 half2 (4 uint4).
    uint32_t h2[16];
#pragma unroll
    for (int k = 0; k < 16; k++) {
        __half2 hh = __floats2half2_rn(s[2 * k][t], s[2 * k + 1][t]);
        h2[k] = *reinterpret_cast<uint32_t*>(&hh);
    }
    uint4 v0 = make_uint4(h2[0], h2[1], h2[2], h2[3]);
    uint4 v1 = make_uint4(h2[4], h2[5], h2[6], h2[7]);
    uint4 v2 = make_uint4(h2[8], h2[9], h2[10], h2[11]);
    uint4 v3 = make_uint4(h2[12], h2[13], h2[14], h2[15]);

    const float* p = xyz + ((size_t)b * NPTS + n) * 3;
    int ix = to_bin(p[0]);
    int iy = to_bin(p[1]);
    int iz = to_bin(p[2]);
    int bins[3] = { ix + RES * iy, iy + RES * iz, ix + RES * iz };

#pragma unroll
    for (int pl = 0; pl < 3; pl++) {
        int sb = pl * NBINS + bins[pl];
        unsigned pos = atomicAdd(&g_cnt[sb], 1u);
        if (pos < CAP) {
            uint4* dst = g_slab + ((size_t)sb * CAP + pos) * 4;
            dst[0] = v0;
            dst[1] = v1;
            dst[2] = v2;
            dst[3] = v3;
        } else {
            // Rare overflow: full-precision accumulate.
            float* o = g_ovf + ((size_t)(b * 3 + pl) * NBINS + bins[pl]) * CH;
#pragma unroll
            for (int k = 0; k < 8; k++)
                red_add_v4(o + 4 * k, s[4 * k][t], s[4 * k + 1][t],
                           s[4 * k + 2][t], s[4 * k + 3][t]);
        }
    }
}

// Warp-per-bin mean for ONE batch. Reads slab (hot in L2), merges overflow,
// resets g_cnt / g_ovf entries it consumed (self-cleaning for graph replays).
// grid (NBINS/32, 3), block 256.
__global__ void mean_kernel(float* __restrict__ out, int b) {
    __shared__ float tile[32][33];
    int pl = blockIdx.y;
    int bin0 = blockIdx.x * 32;
    int warp = threadIdx.x >> 5;
    int lane = threadIdx.x & 31;
    int slotlane = lane >> 2;   // 0..7: slot offset within iteration
    int chgrp = lane & 3;       // 0..3: uint4 index within slot (8 channels)

#pragma unroll
    for (int j = 0; j < 4; j++) {
        int bl = warp * 4 + j;           // 0..31 bin within tile
        int bin = bin0 + bl;
        unsigned cnt = g_cnt[pl * NBINS + bin];
        unsigned m = min(cnt, (unsigned)CAP);
        const uint4* base = g_slab + (size_t)(pl * NBINS + bin) * CAP * 4;

        float2 acc[4] = { {0.f, 0.f}, {0.f, 0.f}, {0.f, 0.f}, {0.f, 0.f} };
        for (unsigned i = 0; i < m; i += 8) {
            unsigned slot = i + slotlane;
            if (slot < m) {
                uint4 v = base[slot * 4 + chgrp];
                float2 f0 = __half22float2(*reinterpret_cast<__half2*>(&v.x));
                float2 f1 = __half22float2(*reinterpret_cast<__half2*>(&v.y));
                float2 f2 = __half22float2(*reinterpret_cast<__half2*>(&v.z));
                float2 f3 = __half22float2(*reinterpret_cast<__half2*>(&v.w));
                acc[0].x += f0.x; acc[0].y += f0.y;
                acc[1].x += f1.x; acc[1].y += f1.y;
                acc[2].x += f2.x; acc[2].y += f2.y;
                acc[3].x += f3.x; acc[3].y += f3.y;
            }
        }
        // Reduce over the 8 slot groups (lanes differing in bits 2..4).
#pragma unroll
        for (int mask = 4; mask <= 16; mask <<= 1) {
#pragma unroll
            for (int k = 0; k < 4; k++) {
                acc[k].x += __shfl_xor_sync(0xffffffffu, acc[k].x, mask);
                acc[k].y += __shfl_xor_sync(0xffffffffu, acc[k].y, mask);
            }
        }
        if (slotlane == 0) {   // lanes 0..3 hold the full f16-slab sums
            if (cnt > CAP) {
                // Merge fp32 overflow partials, then zero them for the next replay.
                float* o = g_ovf + ((size_t)(b * 3 + pl) * NBINS + bin) * CH + chgrp * 8;
                float4 o0 = reinterpret_cast<float4*>(o)[0];
                float4 o1 = reinterpret_cast<float4*>(o)[1];
                acc[0].x += o0.x; acc[0].y += o0.y;
                acc[1].x += o0.z; acc[1].y += o0.w;
                acc[2].x += o1.x; acc[2].y += o1.y;
                acc[3].x += o1.z; acc[3].y += o1.w;
                reinterpret_cast<float4*>(o)[0] = make_float4(0.f, 0.f, 0.f, 0.f);
                reinterpret_cast<float4*>(o)[1] = make_float4(0.f, 0.f, 0.f, 0.f);
            }
            float inv = 1.f / fmaxf((float)cnt, 1.f);
#pragma unroll
            for (int k = 0; k < 4; k++) {
                tile[bl][chgrp * 8 + 2 * k]     = acc[k].x * inv;
                tile[bl][chgrp * 8 + 2 * k + 1] = acc[k].y * inv;
            }
        }
        __syncwarp();
        if (lane == 0) g_cnt[pl * NBINS + bin] = 0u;   // reset for next batch / replay
    }
    __syncthreads();

    size_t obase = ((size_t)(b * 3 + pl) * CH) * NBINS + bin0;
#pragma unroll
    for (int c = warp; c < CH; c += 8)
        out[obase + (size_t)c * NBINS + lane] = tile[lane][c];
}

extern "C" void kernel_launch(void* const* d_in, const int* in_sizes, int n_in,
                              void* d_out, int out_size) {
    const float* xyz = (const float*)d_in[0];    // (B, N, 3)
    const float* feat = (const float*)d_in[1];   // (B, C, N)
    float* out = (float*)d_out;                  // (B, 3, C, R, R)

    int sblocks = (NPTS + 255) / 256;
    dim3 mgrid(NBINS / 32, 3);
    for (int b = 0; b < BATCH; b++) {
        scatter_kernel<<<sblocks, 256>>>(xyz, feat, b);
        mean_kernel<<<mgrid, 256>>>(out, b);
    }
}

// round 11
// speedup vs baseline: 2.8642x; 2.8642x over previous
#include <cuda_runtime.h>
#include <cuda_fp16.h>
#include <cstdint>

#define BATCH 8
#define NPTS 200000
#define CH 32
#define RES 128
#define NBINS (RES * RES)
#define NSEG (BATCH * 3)
#define EPSF 1e-5f

// f16 accumulator, layout (b, plane, bin, channel): one bin = 64B (32 halves).
// 24 * 16384 * 32 * 2B = 25.2 MB.
__device__ __half2 g_accum[(size_t)NSEG * NBINS * (CH / 2)];
__device__ float g_cnt[NSEG * NBINS];

__device__ __forceinline__ void red_add_v4_f16x2(__half2* addr,
                                                 uint32_t a0, uint32_t a1,
                                                 uint32_t a2, uint32_t a3) {
    // One 16B RMW carrying 8 f16 channels (max legal red vector width).
    asm volatile("red.global.add.noftz.v4.f16x2 [%0], {%1,%2,%3,%4};"
                 :: "l"(addr), "r"(a0), "r"(a1), "r"(a2), "r"(a3)
                 : "memory");
}

__device__ __forceinline__ void red_add_f32(float* addr, float v) {
    asm volatile("red.global.add.f32 [%0], %1;"
                 :: "l"(addr), "f"(v)
                 : "memory");
}

__global__ void zero_scratch_kernel() {
    // g_accum as uint4: total half2 count / 4 (uint4 = 16B = 4 half2).  <-- R10 bug was /8
    const size_t n4a = (size_t)NSEG * NBINS * (CH / 2) / 4;
    const size_t n4c = (size_t)NSEG * NBINS / 4;
    uint4 z = make_uint4(0u, 0u, 0u, 0u);
    uint4* a = reinterpret_cast<uint4*>(g_accum);
    uint4* c = reinterpret_cast<uint4*>(g_cnt);
    size_t stride = (size_t)gridDim.x * blockDim.x;
    for (size_t i = (size_t)blockIdx.x * blockDim.x + threadIdx.x; i < n4a; i += stride)
        a[i] = z;
    for (size_t i = (size_t)blockIdx.x * blockDim.x + threadIdx.x; i < n4c; i += stride)
        c[i] = z;
}

__device__ __forceinline__ int to_bin(float v) {
    // Byte-identical to the validated Round-1 formula (matches JAX exactly).
    float t = (v + 1.0f) / 2.0f - 0.5f;
    t = t / (1.0f + EPSF) + 0.5f;
    t = fminf(fmaxf(t, 0.0f), 1.0f - EPSF);
    return (int)(t * 128.0f);
}

// Round-1 structure: thread = point; coalesced strided channel loads;
// payload scatter via 4x v4.f16x2 RED per plane instead of 8x v4.f32.
__global__ void scatter_kernel(const float* __restrict__ xyz,
                               const float* __restrict__ feat) {
    int idx = blockIdx.x * blockDim.x + threadIdx.x;
    if (idx >= BATCH * NPTS) return;
    int b = idx / NPTS;
    int n = idx - b * NPTS;

    const float* p = xyz + (size_t)idx * 3;
    float x = p[0], y = p[1], z = p[2];
    int ix = to_bin(x);
    int iy = to_bin(y);
    int iz = to_bin(z);

    int bin_xy = ix + RES * iy;
    int bin_yz = iy + RES * iz;
    int bin_xz = ix + RES * iz;

    size_t base_b = (size_t)b * 3 * NBINS;
    red_add_f32(&g_cnt[base_b + 0 * NBINS + bin_xy], 1.0f);
    red_add_f32(&g_cnt[base_b + 1 * NBINS + bin_yz], 1.0f);
    red_add_f32(&g_cnt[base_b + 2 * NBINS + bin_xz], 1.0f);

    // Load 32 channels (coalesced across the warp), pack to 16 half2.
    const float* fb = feat + (size_t)b * CH * NPTS + n;
    uint32_t h[16];
#pragma unroll
    for (int k = 0; k < 16; k++) {
        float f0 = __ldg(fb + (size_t)(2 * k) * NPTS);
        float f1 = __ldg(fb + (size_t)(2 * k + 1) * NPTS);
        __half2 hh = __floats2half2_rn(f0, f1);
        h[k] = *reinterpret_cast<uint32_t*>(&hh);
    }

    __half2* a0 = g_accum + (base_b + (size_t)0 * NBINS + bin_xy) * (CH / 2);
    __half2* a1 = g_accum + (base_b + (size_t)1 * NBINS + bin_yz) * (CH / 2);
    __half2* a2 = g_accum + (base_b + (size_t)2 * NBINS + bin_xz) * (CH / 2);

#pragma unroll
    for (int q = 0; q < 4; q++)
        red_add_v4_f16x2(a0 + 4 * q, h[4 * q], h[4 * q + 1], h[4 * q + 2], h[4 * q + 3]);
#pragma unroll
    for (int q = 0; q < 4; q++)
        red_add_v4_f16x2(a1 + 4 * q, h[4 * q], h[4 * q + 1], h[4 * q + 2], h[4 * q + 3]);
#pragma unroll
    for (int q = 0; q < 4; q++)
        red_add_v4_f16x2(a2 + 4 * q, h[4 * q], h[4 * q + 1], h[4 * q + 2], h[4 * q + 3]);
}

// Transpose (bin, channel) -> (channel, bin) with count division.
// Block = 32x32, grid = (NBINS/32, 3, B). Round-1 structure, f16 reads.
__global__ void finalize_kernel(float* __restrict__ out) {
    __shared__ float tile[32][33];
    __shared__ float cnts[32];

    int pix0 = blockIdx.x * 32;
    int pl = blockIdx.y;
    int b = blockIdx.z;
    int tx = threadIdx.x;
    int ty = threadIdx.y;

    size_t base = ((size_t)b * 3 + pl) * NBINS;

    // load: 32 channels contiguous per bin row (64B per row, 2B per thread)
    const __half* arow = reinterpret_cast<const __half*>(g_accum + (base + pix0 + ty) * (CH / 2));
    tile[ty][tx] = __half2float(arow[tx]);
    if (ty == 0) cnts[tx] = g_cnt[base + pix0 + tx];
    __syncthreads();

    float cnt = fmaxf(cnts[tx], 1.0f);
    out[(((size_t)b * 3 + pl) * CH + ty) * NBINS + pix0 + tx] = tile[tx][ty] / cnt;
}

extern "C" void kernel_launch(void* const* d_in, const int* in_sizes, int n_in,
                              void* d_out, int out_size) {
    const float* xyz = (const float*)d_in[0];    // (B, N, 3)
    const float* feat = (const float*)d_in[1];   // (B, C, N)
    float* out = (float*)d_out;                  // (B, 3, C, R, R)

    zero_scratch_kernel<<<2048, 256>>>();

    int total = BATCH * NPTS;
    scatter_kernel<<<(total + 255) / 256, 256>>>(xyz, feat);

    dim3 fgrid(NBINS / 32, 3, BATCH);
    dim3 fblk(32, 32);
    finalize_kernel<<<fgrid, fblk>>>(out);
}